// round 15
// baseline (speedup 1.0000x reference)
#include <cuda_runtime.h>
#include <math.h>
#include <stdint.h>

// Problem constants (fixed by setup_inputs)
#define G     8
#define HID   4000
#define Q     512
#define QG    64      // Q / G
#define LWIN  6       // L
#define INSZ  76      // QG + 2*L
#define STEPS 400
#define EPS   32
#define NHIST 64      // u_hist rows

#define NROWS (G * HID)          // 32000 W_hh rows
#define BXG   18                 // blocks per group (grid 144 = 1/SM)
#define TPG   500                // 8-row tiles per group
#define TILE_BYTES 64000         // 8 rows * 4000 shorts * 2B
#define NSTAGE 3
#define NTHREADS 288             // 8 consumer warps + 1 producer warp
#define KEEP  11                 // leading tiles per block kept L2-resident (~101MB)

#define OROWS (G * QG)           // 512 W_out rows
#define OWID  8000               // 2*HID

// smem layout offsets (bytes)
#define SM_H    0                 // 4000 floats = 16000
#define SM_U    16000             // INSZ floats (padded to 512)
#define SM_MBAR 16512             // full[3] @ +0, empty[3] @ +24
#define SM_BUF  16576             // 3 * 64000
#define SM_TOTAL (SM_BUF + NSTAGE * TILE_BYTES)   // 208576

// Scratch
__device__ float g_h[2][G * HID];
__device__ __align__(256) short g_Wq[(size_t)NROWS * HID];   // 256 MB int16 W_hh
__device__ float g_ds[NROWS];                                // W_hh scale per row
__device__ __align__(256) short g_Wo[(size_t)OROWS * OWID];  // 8 MB int16 W_out
__device__ float g_dso[OROWS];                               // W_out scale per row
__device__ __align__(256) short g_Wi[(size_t)NROWS * INSZ];  // 4.9 MB int16 W_in
__device__ float g_dsi[NROWS];                               // W_in scale per row

// ---------------------------------------------------------------------------
// async / mbarrier helpers
// ---------------------------------------------------------------------------
__device__ __forceinline__ void mbar_init(uint32_t mbar, uint32_t count)
{
    asm volatile("mbarrier.init.shared.b64 [%0], %1;" :: "r"(mbar), "r"(count) : "memory");
}
__device__ __forceinline__ void mbar_expect_tx(uint32_t mbar, uint32_t bytes)
{
    asm volatile("mbarrier.arrive.expect_tx.shared.b64 _, [%0], %1;"
                 :: "r"(mbar), "r"(bytes) : "memory");
}
__device__ __forceinline__ void mbar_arrive(uint32_t mbar)
{
    asm volatile("mbarrier.arrive.shared.b64 _, [%0];" :: "r"(mbar) : "memory");
}
__device__ __forceinline__ void bulk_g2s_pol(uint32_t dst, const void* src,
                                             uint32_t bytes, uint32_t mbar,
                                             uint64_t pol)
{
    asm volatile("cp.async.bulk.shared::cta.global.mbarrier::complete_tx::bytes"
                 ".L2::cache_hint [%0], [%1], %2, [%3], %4;"
                 :: "r"(dst), "l"(src), "r"(bytes), "r"(mbar), "l"(pol) : "memory");
}
__device__ __forceinline__ void mbar_wait(uint32_t mbar, uint32_t parity)
{
    asm volatile(
        "{\n\t"
        ".reg .pred P;\n\t"
        "WAIT_%=:\n\t"
        "mbarrier.try_wait.parity.acquire.cta.shared::cta.b64 P, [%0], %1, 0x989680;\n\t"
        "@P bra DONE_%=;\n\t"
        "bra WAIT_%=;\n\t"
        "DONE_%=:\n\t"
        "}"
        :: "r"(mbar), "r"(parity) : "memory");
}

// ---------------------------------------------------------------------------
// One-pass W_hh quantizer: one row per block, row staged in smem so the
// 1 GB fp32 source is read ONCE per replay (was twice).
// ---------------------------------------------------------------------------
__global__ void __launch_bounds__(256) quant_whh_kernel(const float* __restrict__ W_hh)
{
    __shared__ __align__(16) float buf[HID];
    __shared__ float red[8];
    __shared__ float s_qs;

    const int row = blockIdx.x;
    const int tid = threadIdx.x;
    const int warp = tid >> 5;
    const int lane = tid & 31;

    const float4* src = (const float4*)(W_hh + (size_t)row * HID);
    float4* bufv = (float4*)buf;

    float m = 0.0f;
    for (int j = tid; j < HID / 4; j += 256) {
        float4 v = src[j];
        bufv[j] = v;
        m = fmaxf(m, fmaxf(fmaxf(fabsf(v.x), fabsf(v.y)),
                           fmaxf(fabsf(v.z), fabsf(v.w))));
    }
    #pragma unroll
    for (int off = 16; off; off >>= 1)
        m = fmaxf(m, __shfl_xor_sync(0xffffffffu, m, off));
    if (lane == 0) red[warp] = m;
    __syncthreads();
    if (tid == 0) {
        float mm = red[0];
        #pragma unroll
        for (int w = 1; w < 8; ++w) mm = fmaxf(mm, red[w]);
        g_ds[row] = (mm > 0.0f) ? (mm / 32767.0f) : 0.0f;
        s_qs = (mm > 0.0f) ? (32767.0f / mm) : 0.0f;
    }
    __syncthreads();

    const float qs = s_qs;
    uint2* dst = (uint2*)(g_Wq + (size_t)row * HID);
    for (int j = tid; j < HID / 4; j += 256) {
        float4 v = bufv[j];
        int s0 = __float2int_rn(fminf(fmaxf(v.x * qs, -32767.0f), 32767.0f));
        int s1 = __float2int_rn(fminf(fmaxf(v.y * qs, -32767.0f), 32767.0f));
        int s2 = __float2int_rn(fminf(fmaxf(v.z * qs, -32767.0f), 32767.0f));
        int s3 = __float2int_rn(fminf(fmaxf(v.w * qs, -32767.0f), 32767.0f));
        uint2 p;
        p.x = (s0 & 0xffff) | (s1 << 16);
        p.y = (s2 & 0xffff) | (s3 << 16);
        dst[j] = p;
    }
}

// ---------------------------------------------------------------------------
// Generic per-row absmax int16 quantizer (row stride = wpad) — W_out / W_in.
// ---------------------------------------------------------------------------
__global__ void __launch_bounds__(256) quant_rows_kernel(
    const float* __restrict__ W, short* __restrict__ dst_base,
    float* __restrict__ ds, int width, int wpad)
{
    const int warp = threadIdx.x >> 5;
    const int lane = threadIdx.x & 31;
    const int row  = blockIdx.x * 8 + warp;

    const float4* w4 = (const float4*)(W + (size_t)row * width);
    const int nf4 = width / 4;

    float m = 0.0f;
    for (int j = lane; j < nf4; j += 32) {
        float4 v = w4[j];
        m = fmaxf(m, fmaxf(fmaxf(fabsf(v.x), fabsf(v.y)),
                           fmaxf(fabsf(v.z), fabsf(v.w))));
    }
    #pragma unroll
    for (int off = 16; off; off >>= 1)
        m = fmaxf(m, __shfl_xor_sync(0xffffffffu, m, off));

    const float qs = (m > 0.0f) ? (32767.0f / m) : 0.0f;
    if (lane == 0)
        ds[row] = (m > 0.0f) ? (m / 32767.0f) : 0.0f;

    uint2* dst = (uint2*)(dst_base + (size_t)row * wpad);
    for (int j = lane; j < nf4; j += 32) {
        float4 v = w4[j];
        int s0 = __float2int_rn(fminf(fmaxf(v.x * qs, -32767.0f), 32767.0f));
        int s1 = __float2int_rn(fminf(fmaxf(v.y * qs, -32767.0f), 32767.0f));
        int s2 = __float2int_rn(fminf(fmaxf(v.z * qs, -32767.0f), 32767.0f));
        int s3 = __float2int_rn(fminf(fmaxf(v.w * qs, -32767.0f), 32767.0f));
        uint2 p;
        p.x = (s0 & 0xffff) | (s1 << 16);
        p.y = (s2 & 0xffff) | (s3 << 16);
        dst[j] = p;
    }
    uint2 z; z.x = 0; z.y = 0;
    for (int j = nf4 + lane; j < wpad / 4; j += 32)
        dst[j] = z;
}

// 8 int16 weights (one int4) against 8 h values (two float4)
__device__ __forceinline__ void dotq(int4 w, float4 ha, float4 hb, float& acc)
{
    acc += (float)((short)w.x) * ha.x + (float)(w.x >> 16) * ha.y;
    acc += (float)((short)w.y) * ha.z + (float)(w.y >> 16) * ha.w;
    acc += (float)((short)w.z) * hb.x + (float)(w.z >> 16) * hb.y;
    acc += (float)((short)w.w) * hb.z + (float)(w.w >> 16) * hb.w;
}

// ---------------------------------------------------------------------------
// One ESN step. W_hh via cp.async.bulk ring; first KEEP tiles per block are
// L2::evict_last (stable resident set, persists across graph-replayed
// launches), the rest L2::evict_first so the stream can't evict it.
// grid = (18, G) = 144 blocks = 1/SM. block = 288 (8 consumers + producer).
// ---------------------------------------------------------------------------
__global__ void __launch_bounds__(NTHREADS, 1) step_kernel(
    const float* __restrict__ u,      // [Q]
    const float* __restrict__ h_in,   // [G, HID]
    float*       __restrict__ h_out)  // [G, HID]
{
    extern __shared__ __align__(128) char smem[];
    float* sh_h = (float*)(smem + SM_H);
    float* sh_u = (float*)(smem + SM_U);

    const int g   = blockIdx.y;
    const int bx  = blockIdx.x;
    const int tid = threadIdx.x;

    const uint32_t smem_base = (uint32_t)__cvta_generic_to_shared(smem);
    const uint32_t mb_full   = smem_base + SM_MBAR;        // 3 x 8B
    const uint32_t mb_empty  = smem_base + SM_MBAR + 24;   // 3 x 8B

    for (int i = tid; i < HID; i += NTHREADS)
        sh_h[i] = h_in[g * HID + i];
    if (tid < INSZ)
        sh_u[tid] = u[(g * QG - LWIN + tid + Q) & (Q - 1)];  // periodic window

    if (tid == 0) {
        #pragma unroll
        for (int s = 0; s < NSTAGE; ++s) {
            mbar_init(mb_full + s * 8, 1);
            mbar_init(mb_empty + s * 8, 8);
        }
        asm volatile("fence.proxy.async.shared::cta;" ::: "memory");
    }
    __syncthreads();

    const int ntiles = (TPG - bx + BXG - 1) / BXG;   // 27 or 28
    const int warp = tid >> 5;
    const int lane = tid & 31;

    if (warp == 8) {
        // ---------------- producer ----------------
        if (lane == 0) {
            uint64_t pol_keep, pol_stream;
            asm volatile("createpolicy.fractional.L2::evict_last.b64 %0, 1.0;"
                         : "=l"(pol_keep));
            asm volatile("createpolicy.fractional.L2::evict_first.b64 %0, 1.0;"
                         : "=l"(pol_stream));
            int st = 0, ph = 1;          // phase=1: first 3 empty-waits pass
            for (int i = 0; i < ntiles; ++i) {
                mbar_wait(mb_empty + st * 8, (uint32_t)ph);
                const int tile = bx + BXG * i;
                const void* src =
                    g_Wq + ((size_t)g * HID + (size_t)tile * 8) * HID;
                mbar_expect_tx(mb_full + st * 8, TILE_BYTES);
                bulk_g2s_pol(smem_base + SM_BUF + st * TILE_BYTES, src,
                             TILE_BYTES, mb_full + st * 8,
                             (i < KEEP) ? pol_keep : pol_stream);
                if (++st == NSTAGE) { st = 0; ph ^= 1; }
            }
        }
        return;
    }

    // ---------------- consumers (warps 0..7) ----------------
    // preload this lane's h slice into registers
    float4 hreg[32];
    const float4* sh4 = (const float4*)sh_h;
    #pragma unroll
    for (int k = 0; k < 15; ++k) {
        hreg[2 * k]     = sh4[k * 64 + lane * 2];
        hreg[2 * k + 1] = sh4[k * 64 + lane * 2 + 1];
    }
    if (lane < 20) {
        hreg[30] = sh4[960 + lane * 2];
        hreg[31] = sh4[961 + lane * 2];
    }

    int st = 0, ph = 0;
    for (int i = 0; i < ntiles; ++i) {
        const int tile = bx + BXG * i;

        mbar_wait(mb_full + st * 8, (uint32_t)ph);

        // warp w -> row tile*8 + w; 4000 shorts = 500 int4
        const int4* w4 =
            (const int4*)(smem + SM_BUF + st * TILE_BYTES) + warp * 500;

        float a0 = 0.0f, a1 = 0.0f, a2 = 0.0f, a3 = 0.0f;
        #pragma unroll
        for (int k = 0; k < 15; ++k) {
            int4 w = w4[k * 32 + lane];
            float& acc = (k & 3) == 0 ? a0 : (k & 3) == 1 ? a1 : (k & 3) == 2 ? a2 : a3;
            dotq(w, hreg[2 * k], hreg[2 * k + 1], acc);
        }
        if (lane < 20) {
            int4 w = w4[480 + lane];
            dotq(w, hreg[30], hreg[31], a3);
        }
        float acc = (a0 + a1) + (a2 + a3);     // depends on all tile loads

        if (lane == 0)
            mbar_arrive(mb_empty + st * 8);    // free buffer; refill overlaps epilogue

        const int r    = tile * 8 + warp;      // row within group
        const int grow = g * HID + r;
        acc *= g_ds[grow];

        const short* wi = g_Wi + (size_t)grow * INSZ;
        float ai = 0.0f;
        #pragma unroll
        for (int o = lane; o < INSZ; o += 32)
            ai += (float)wi[o] * sh_u[o];
        acc += ai * g_dsi[grow];

        #pragma unroll
        for (int off = 16; off; off >>= 1)
            acc += __shfl_xor_sync(0xffffffffu, acc, off);

        if (lane == 0)
            h_out[grow] = 0.4f * sh_h[r] + 0.6f * tanhf(acc);

        if (++st == NSTAGE) { st = 0; ph ^= 1; }
    }
}

// ---------------------------------------------------------------------------
// Readout with int16 W_out: y[g*64+o] = dso * (Wo[g,o,:] . [h ; h*h])
// ---------------------------------------------------------------------------
__global__ void __launch_bounds__(256) readout_kernel(
    const float* __restrict__ h,      // [G, HID]
    float*       __restrict__ y)      // [Q]
{
    __shared__ __align__(16) float sh_h[HID];
    __shared__ float sh_red[8];

    const int g   = blockIdx.y;
    const int o   = blockIdx.x;
    const int tid = threadIdx.x;

    for (int i = tid; i < HID; i += 256)
        sh_h[i] = h[g * HID + i];
    __syncthreads();

    const float4* sh4 = (const float4*)sh_h;
    const int row = g * QG + o;
    const int4* w4 = (const int4*)(g_Wo + (size_t)row * OWID);   // 1000 int4

    float acc = 0.0f;
    #pragma unroll 2
    for (int j = tid; j < HID / 8; j += 256) {
        int4 w = w4[j];
        dotq(w, sh4[2 * j], sh4[2 * j + 1], acc);
    }
    #pragma unroll 2
    for (int j = tid; j < HID / 8; j += 256) {
        int4 w = w4[HID / 8 + j];
        float4 ha = sh4[2 * j], hb = sh4[2 * j + 1];
        ha.x *= ha.x; ha.y *= ha.y; ha.z *= ha.z; ha.w *= ha.w;
        hb.x *= hb.x; hb.y *= hb.y; hb.z *= hb.z; hb.w *= hb.w;
        dotq(w, ha, hb, acc);
    }

    const int warp = tid >> 5;
    const int lane = tid & 31;
    #pragma unroll
    for (int off = 16; off; off >>= 1)
        acc += __shfl_xor_sync(0xffffffffu, acc, off);
    if (lane == 0) sh_red[warp] = acc;
    __syncthreads();
    if (warp == 0) {
        float v = (lane < 8) ? sh_red[lane] : 0.0f;
        #pragma unroll
        for (int off = 4; off; off >>= 1)
            v += __shfl_xor_sync(0xffffffffu, v, off);
        if (lane == 0) y[row] = v * g_dso[row];
    }
}

// ---------------------------------------------------------------------------
// Launch sequence: quantize W_hh + W_out + W_in, warmup, 400 step+readout.
// ---------------------------------------------------------------------------
extern "C" void kernel_launch(void* const* d_in, const int* in_sizes, int n_in,
                              void* d_out, int out_size)
{
    const float* u_hist = (const float*)d_in[0];   // [64, 512]
    const float* W_in   = (const float*)d_in[1];   // [8, 4000, 76]
    const float* W_hh   = (const float*)d_in[2];   // [8, 4000, 4000]
    const float* W_out  = (const float*)d_in[3];   // [8, 64, 8000]
    float*       out    = (float*)d_out;           // [400, 512]

    float* hbase = nullptr;
    cudaGetSymbolAddress((void**)&hbase, g_h);
    cudaMemsetAsync(hbase, 0, sizeof(float) * G * HID, 0);

    short* wo = nullptr;   cudaGetSymbolAddress((void**)&wo,   g_Wo);
    float* dso = nullptr;  cudaGetSymbolAddress((void**)&dso,  g_dso);
    short* wi = nullptr;   cudaGetSymbolAddress((void**)&wi,   g_Wi);
    float* dsi = nullptr;  cudaGetSymbolAddress((void**)&dsi,  g_dsi);

    cudaFuncSetAttribute(step_kernel,
                         cudaFuncAttributeMaxDynamicSharedMemorySize, SM_TOTAL);

    quant_whh_kernel<<<NROWS, 256>>>(W_hh);
    quant_rows_kernel<<<OROWS / 8, 256>>>(W_out, wo, dso, OWID, OWID);
    quant_rows_kernel<<<NROWS / 8, 256>>>(W_in, wi, dsi, INSZ, INSZ);

    const dim3 sgrid(BXG, G);      // 144 blocks = 1/SM
    const dim3 rgrid(QG, G);       // 512 blocks

    float* hb[2] = { hbase, hbase + G * HID };

    for (int t = 0; t < EPS; ++t) {
        const float* u = u_hist + (size_t)(NHIST - EPS + t) * Q;
        step_kernel<<<sgrid, NTHREADS, SM_TOTAL>>>(u, hb[t & 1], hb[(t + 1) & 1]);
    }

    for (int s = 0; s < STEPS; ++s) {
        const float* u = (s == 0) ? (u_hist + (size_t)(NHIST - 1) * Q)
                                  : (out + (size_t)(s - 1) * Q);
        step_kernel<<<sgrid, NTHREADS, SM_TOTAL>>>(u, hb[s & 1], hb[(s + 1) & 1]);
        readout_kernel<<<rgrid, 256>>>(hb[(s + 1) & 1], out + (size_t)s * Q);
    }
}

// round 17
// speedup vs baseline: 1.0924x; 1.0924x over previous
#include <cuda_runtime.h>
#include <math.h>
#include <stdint.h>

// Problem constants (fixed by setup_inputs)
#define G     8
#define HID   4000
#define Q     512
#define QG    64      // Q / G
#define LWIN  6       // L
#define INSZ  76      // QG + 2*L
#define STEPS 400
#define EPS   32
#define NHIST 64      // u_hist rows

#define NROWS (G * HID)          // 32000 W_hh rows
#define BXG   18                 // blocks per group (grid 144 = 1/SM)
#define TPG   500                // 8-row tiles per group
#define TILE_BYTES 64000         // 8 rows * 4000 shorts * 2B
#define NSTAGE 3
#define NTHREADS 288             // 8 consumer warps + 1 producer warp
#define KEEP  9                  // leading tiles per block kept L2-resident (~83MB)

#define OROWS (G * QG)           // 512 W_out rows
#define OWID  8000               // 2*HID

// smem layout offsets (bytes)
#define SM_H    0                 // 4000 floats = 16000
#define SM_U    16000             // INSZ floats (padded to 512)
#define SM_MBAR 16512             // full[3] @ +0, empty[3] @ +24
#define SM_BUF  16576             // 3 * 64000
#define SM_TOTAL (SM_BUF + NSTAGE * TILE_BYTES)   // 208576

// Scratch
__device__ float g_h[2][G * HID];
__device__ __align__(256) short g_Wq[(size_t)NROWS * HID];   // 256 MB int16 W_hh
__device__ float g_ds[NROWS];                                // W_hh scale per row
__device__ __align__(256) short g_Wo[(size_t)OROWS * OWID];  // 8 MB int16 W_out
__device__ float g_dso[OROWS];                               // W_out scale per row
__device__ __align__(256) short g_Wi[(size_t)NROWS * INSZ];  // 4.9 MB int16 W_in
__device__ float g_dsi[NROWS];                               // W_in scale per row

// ---------------------------------------------------------------------------
// async / mbarrier helpers
// ---------------------------------------------------------------------------
__device__ __forceinline__ void mbar_init(uint32_t mbar, uint32_t count)
{
    asm volatile("mbarrier.init.shared.b64 [%0], %1;" :: "r"(mbar), "r"(count) : "memory");
}
__device__ __forceinline__ void mbar_expect_tx(uint32_t mbar, uint32_t bytes)
{
    asm volatile("mbarrier.arrive.expect_tx.shared.b64 _, [%0], %1;"
                 :: "r"(mbar), "r"(bytes) : "memory");
}
__device__ __forceinline__ void mbar_arrive(uint32_t mbar)
{
    asm volatile("mbarrier.arrive.shared.b64 _, [%0];" :: "r"(mbar) : "memory");
}
__device__ __forceinline__ void bulk_g2s_pol(uint32_t dst, const void* src,
                                             uint32_t bytes, uint32_t mbar,
                                             uint64_t pol)
{
    asm volatile("cp.async.bulk.shared::cta.global.mbarrier::complete_tx::bytes"
                 ".L2::cache_hint [%0], [%1], %2, [%3], %4;"
                 :: "r"(dst), "l"(src), "r"(bytes), "r"(mbar), "l"(pol) : "memory");
}
__device__ __forceinline__ void mbar_wait(uint32_t mbar, uint32_t parity)
{
    asm volatile(
        "{\n\t"
        ".reg .pred P;\n\t"
        "WAIT_%=:\n\t"
        "mbarrier.try_wait.parity.acquire.cta.shared::cta.b64 P, [%0], %1, 0x989680;\n\t"
        "@P bra DONE_%=;\n\t"
        "bra WAIT_%=;\n\t"
        "DONE_%=:\n\t"
        "}"
        :: "r"(mbar), "r"(parity) : "memory");
}

// ---------------------------------------------------------------------------
// One-pass W_hh quantizer: one row per block, row staged in smem so the
// 1 GB fp32 source is read ONCE per replay.
// ---------------------------------------------------------------------------
__global__ void __launch_bounds__(256) quant_whh_kernel(const float* __restrict__ W_hh)
{
    __shared__ __align__(16) float buf[HID];
    __shared__ float red[8];
    __shared__ float s_qs;

    const int row = blockIdx.x;
    const int tid = threadIdx.x;
    const int warp = tid >> 5;
    const int lane = tid & 31;

    const float4* src = (const float4*)(W_hh + (size_t)row * HID);
    float4* bufv = (float4*)buf;

    float m = 0.0f;
    for (int j = tid; j < HID / 4; j += 256) {
        float4 v = src[j];
        bufv[j] = v;
        m = fmaxf(m, fmaxf(fmaxf(fabsf(v.x), fabsf(v.y)),
                           fmaxf(fabsf(v.z), fabsf(v.w))));
    }
    #pragma unroll
    for (int off = 16; off; off >>= 1)
        m = fmaxf(m, __shfl_xor_sync(0xffffffffu, m, off));
    if (lane == 0) red[warp] = m;
    __syncthreads();
    if (tid == 0) {
        float mm = red[0];
        #pragma unroll
        for (int w = 1; w < 8; ++w) mm = fmaxf(mm, red[w]);
        g_ds[row] = (mm > 0.0f) ? (mm / 32767.0f) : 0.0f;
        s_qs = (mm > 0.0f) ? (32767.0f / mm) : 0.0f;
    }
    __syncthreads();

    const float qs = s_qs;
    uint2* dst = (uint2*)(g_Wq + (size_t)row * HID);
    for (int j = tid; j < HID / 4; j += 256) {
        float4 v = bufv[j];
        int s0 = __float2int_rn(fminf(fmaxf(v.x * qs, -32767.0f), 32767.0f));
        int s1 = __float2int_rn(fminf(fmaxf(v.y * qs, -32767.0f), 32767.0f));
        int s2 = __float2int_rn(fminf(fmaxf(v.z * qs, -32767.0f), 32767.0f));
        int s3 = __float2int_rn(fminf(fmaxf(v.w * qs, -32767.0f), 32767.0f));
        uint2 p;
        p.x = (s0 & 0xffff) | (s1 << 16);
        p.y = (s2 & 0xffff) | (s3 << 16);
        dst[j] = p;
    }
}

// ---------------------------------------------------------------------------
// Generic per-row absmax int16 quantizer (row stride = wpad) — W_out / W_in.
// ---------------------------------------------------------------------------
__global__ void __launch_bounds__(256) quant_rows_kernel(
    const float* __restrict__ W, short* __restrict__ dst_base,
    float* __restrict__ ds, int width, int wpad)
{
    const int warp = threadIdx.x >> 5;
    const int lane = threadIdx.x & 31;
    const int row  = blockIdx.x * 8 + warp;

    const float4* w4 = (const float4*)(W + (size_t)row * width);
    const int nf4 = width / 4;

    float m = 0.0f;
    for (int j = lane; j < nf4; j += 32) {
        float4 v = w4[j];
        m = fmaxf(m, fmaxf(fmaxf(fabsf(v.x), fabsf(v.y)),
                           fmaxf(fabsf(v.z), fabsf(v.w))));
    }
    #pragma unroll
    for (int off = 16; off; off >>= 1)
        m = fmaxf(m, __shfl_xor_sync(0xffffffffu, m, off));

    const float qs = (m > 0.0f) ? (32767.0f / m) : 0.0f;
    if (lane == 0)
        ds[row] = (m > 0.0f) ? (m / 32767.0f) : 0.0f;

    uint2* dst = (uint2*)(dst_base + (size_t)row * wpad);
    for (int j = lane; j < nf4; j += 32) {
        float4 v = w4[j];
        int s0 = __float2int_rn(fminf(fmaxf(v.x * qs, -32767.0f), 32767.0f));
        int s1 = __float2int_rn(fminf(fmaxf(v.y * qs, -32767.0f), 32767.0f));
        int s2 = __float2int_rn(fminf(fmaxf(v.z * qs, -32767.0f), 32767.0f));
        int s3 = __float2int_rn(fminf(fmaxf(v.w * qs, -32767.0f), 32767.0f));
        uint2 p;
        p.x = (s0 & 0xffff) | (s1 << 16);
        p.y = (s2 & 0xffff) | (s3 << 16);
        dst[j] = p;
    }
    uint2 z; z.x = 0; z.y = 0;
    for (int j = nf4 + lane; j < wpad / 4; j += 32)
        dst[j] = z;
}

// 8 int16 weights (one int4) against 8 h values (two float4)
__device__ __forceinline__ void dotq(int4 w, float4 ha, float4 hb, float& acc)
{
    acc += (float)((short)w.x) * ha.x + (float)(w.x >> 16) * ha.y;
    acc += (float)((short)w.y) * ha.z + (float)(w.y >> 16) * ha.w;
    acc += (float)((short)w.z) * hb.x + (float)(w.z >> 16) * hb.y;
    acc += (float)((short)w.w) * hb.z + (float)(w.w >> 16) * hb.w;
}

// ---------------------------------------------------------------------------
// One ESN step. W_hh via cp.async.bulk ring; first KEEP tiles per block are
// L2::evict_last (stable ~83MB resident set, persists across graph-replayed
// launches), the rest L2::evict_first so the stream can't evict it.
// grid = (18, G) = 144 blocks = 1/SM. block = 288 (8 consumers + producer).
// ---------------------------------------------------------------------------
__global__ void __launch_bounds__(NTHREADS, 1) step_kernel(
    const float* __restrict__ u,      // [Q]
    const float* __restrict__ h_in,   // [G, HID]
    float*       __restrict__ h_out)  // [G, HID]
{
    extern __shared__ __align__(128) char smem[];
    float* sh_h = (float*)(smem + SM_H);
    float* sh_u = (float*)(smem + SM_U);

    const int g   = blockIdx.y;
    const int bx  = blockIdx.x;
    const int tid = threadIdx.x;

    const uint32_t smem_base = (uint32_t)__cvta_generic_to_shared(smem);
    const uint32_t mb_full   = smem_base + SM_MBAR;        // 3 x 8B
    const uint32_t mb_empty  = smem_base + SM_MBAR + 24;   // 3 x 8B

    for (int i = tid; i < HID; i += NTHREADS)
        sh_h[i] = h_in[g * HID + i];
    if (tid < INSZ)
        sh_u[tid] = u[(g * QG - LWIN + tid + Q) & (Q - 1)];  // periodic window

    if (tid == 0) {
        #pragma unroll
        for (int s = 0; s < NSTAGE; ++s) {
            mbar_init(mb_full + s * 8, 1);
            mbar_init(mb_empty + s * 8, 8);
        }
        asm volatile("fence.proxy.async.shared::cta;" ::: "memory");
    }
    __syncthreads();

    const int ntiles = (TPG - bx + BXG - 1) / BXG;   // 27 or 28
    const int warp = tid >> 5;
    const int lane = tid & 31;

    if (warp == 8) {
        // ---------------- producer ----------------
        if (lane == 0) {
            uint64_t pol_keep, pol_stream;
            asm volatile("createpolicy.fractional.L2::evict_last.b64 %0, 1.0;"
                         : "=l"(pol_keep));
            asm volatile("createpolicy.fractional.L2::evict_first.b64 %0, 1.0;"
                         : "=l"(pol_stream));
            int st = 0, ph = 1;          // phase=1: first 3 empty-waits pass
            for (int i = 0; i < ntiles; ++i) {
                mbar_wait(mb_empty + st * 8, (uint32_t)ph);
                const int tile = bx + BXG * i;
                const void* src =
                    g_Wq + ((size_t)g * HID + (size_t)tile * 8) * HID;
                mbar_expect_tx(mb_full + st * 8, TILE_BYTES);
                bulk_g2s_pol(smem_base + SM_BUF + st * TILE_BYTES, src,
                             TILE_BYTES, mb_full + st * 8,
                             (i < KEEP) ? pol_keep : pol_stream);
                if (++st == NSTAGE) { st = 0; ph ^= 1; }
            }
        }
        return;
    }

    // ---------------- consumers (warps 0..7) ----------------
    // preload this lane's h slice into registers
    float4 hreg[32];
    const float4* sh4 = (const float4*)sh_h;
    #pragma unroll
    for (int k = 0; k < 15; ++k) {
        hreg[2 * k]     = sh4[k * 64 + lane * 2];
        hreg[2 * k + 1] = sh4[k * 64 + lane * 2 + 1];
    }
    if (lane < 20) {
        hreg[30] = sh4[960 + lane * 2];
        hreg[31] = sh4[961 + lane * 2];
    }

    int st = 0, ph = 0;
    for (int i = 0; i < ntiles; ++i) {
        const int tile = bx + BXG * i;

        mbar_wait(mb_full + st * 8, (uint32_t)ph);

        // warp w -> row tile*8 + w; 4000 shorts = 500 int4
        const int4* w4 =
            (const int4*)(smem + SM_BUF + st * TILE_BYTES) + warp * 500;

        float a0 = 0.0f, a1 = 0.0f, a2 = 0.0f, a3 = 0.0f;
        #pragma unroll
        for (int k = 0; k < 15; ++k) {
            int4 w = w4[k * 32 + lane];
            float& acc = (k & 3) == 0 ? a0 : (k & 3) == 1 ? a1 : (k & 3) == 2 ? a2 : a3;
            dotq(w, hreg[2 * k], hreg[2 * k + 1], acc);
        }
        if (lane < 20) {
            int4 w = w4[480 + lane];
            dotq(w, hreg[30], hreg[31], a3);
        }
        float acc = (a0 + a1) + (a2 + a3);     // depends on all tile loads

        if (lane == 0)
            mbar_arrive(mb_empty + st * 8);    // free buffer; refill overlaps epilogue

        const int r    = tile * 8 + warp;      // row within group
        const int grow = g * HID + r;
        acc *= g_ds[grow];

        const short* wi = g_Wi + (size_t)grow * INSZ;
        float ai = 0.0f;
        #pragma unroll
        for (int o = lane; o < INSZ; o += 32)
            ai += (float)wi[o] * sh_u[o];
        acc += ai * g_dsi[grow];

        #pragma unroll
        for (int off = 16; off; off >>= 1)
            acc += __shfl_xor_sync(0xffffffffu, acc, off);

        if (lane == 0)
            h_out[grow] = 0.4f * sh_h[r] + 0.6f * tanhf(acc);

        if (++st == NSTAGE) { st = 0; ph ^= 1; }
    }
}

// ---------------------------------------------------------------------------
// Readout with int16 W_out: y[g*64+o] = dso * (Wo[g,o,:] . [h ; h*h])
// ---------------------------------------------------------------------------
__global__ void __launch_bounds__(256) readout_kernel(
    const float* __restrict__ h,      // [G, HID]
    float*       __restrict__ y)      // [Q]
{
    __shared__ __align__(16) float sh_h[HID];
    __shared__ float sh_red[8];

    const int g   = blockIdx.y;
    const int o   = blockIdx.x;
    const int tid = threadIdx.x;

    for (int i = tid; i < HID; i += 256)
        sh_h[i] = h[g * HID + i];
    __syncthreads();

    const float4* sh4 = (const float4*)sh_h;
    const int row = g * QG + o;
    const int4* w4 = (const int4*)(g_Wo + (size_t)row * OWID);   // 1000 int4

    float acc = 0.0f;
    #pragma unroll 2
    for (int j = tid; j < HID / 8; j += 256) {
        int4 w = w4[j];
        dotq(w, sh4[2 * j], sh4[2 * j + 1], acc);
    }
    #pragma unroll 2
    for (int j = tid; j < HID / 8; j += 256) {
        int4 w = w4[HID / 8 + j];
        float4 ha = sh4[2 * j], hb = sh4[2 * j + 1];
        ha.x *= ha.x; ha.y *= ha.y; ha.z *= ha.z; ha.w *= ha.w;
        hb.x *= hb.x; hb.y *= hb.y; hb.z *= hb.z; hb.w *= hb.w;
        dotq(w, ha, hb, acc);
    }

    const int warp = tid >> 5;
    const int lane = tid & 31;
    #pragma unroll
    for (int off = 16; off; off >>= 1)
        acc += __shfl_xor_sync(0xffffffffu, acc, off);
    if (lane == 0) sh_red[warp] = acc;
    __syncthreads();
    if (warp == 0) {
        float v = (lane < 8) ? sh_red[lane] : 0.0f;
        #pragma unroll
        for (int off = 4; off; off >>= 1)
            v += __shfl_xor_sync(0xffffffffu, v, off);
        if (lane == 0) y[row] = v * g_dso[row];
    }
}

// ---------------------------------------------------------------------------
// Launch sequence: quantize W_hh + W_out + W_in, warmup, 400 step+readout.
// ---------------------------------------------------------------------------
extern "C" void kernel_launch(void* const* d_in, const int* in_sizes, int n_in,
                              void* d_out, int out_size)
{
    const float* u_hist = (const float*)d_in[0];   // [64, 512]
    const float* W_in   = (const float*)d_in[1];   // [8, 4000, 76]
    const float* W_hh   = (const float*)d_in[2];   // [8, 4000, 4000]
    const float* W_out  = (const float*)d_in[3];   // [8, 64, 8000]
    float*       out    = (float*)d_out;           // [400, 512]

    float* hbase = nullptr;
    cudaGetSymbolAddress((void**)&hbase, g_h);
    cudaMemsetAsync(hbase, 0, sizeof(float) * G * HID, 0);

    short* wo = nullptr;   cudaGetSymbolAddress((void**)&wo,   g_Wo);
    float* dso = nullptr;  cudaGetSymbolAddress((void**)&dso,  g_dso);
    short* wi = nullptr;   cudaGetSymbolAddress((void**)&wi,   g_Wi);
    float* dsi = nullptr;  cudaGetSymbolAddress((void**)&dsi,  g_dsi);

    cudaFuncSetAttribute(step_kernel,
                         cudaFuncAttributeMaxDynamicSharedMemorySize, SM_TOTAL);

    quant_whh_kernel<<<NROWS, 256>>>(W_hh);
    quant_rows_kernel<<<OROWS / 8, 256>>>(W_out, wo, dso, OWID, OWID);
    quant_rows_kernel<<<NROWS / 8, 256>>>(W_in, wi, dsi, INSZ, INSZ);

    const dim3 sgrid(BXG, G);      // 144 blocks = 1/SM
    const dim3 rgrid(QG, G);       // 512 blocks

    float* hb[2] = { hbase, hbase + G * HID };

    for (int t = 0; t < EPS; ++t) {
        const float* u = u_hist + (size_t)(NHIST - EPS + t) * Q;
        step_kernel<<<sgrid, NTHREADS, SM_TOTAL>>>(u, hb[t & 1], hb[(t + 1) & 1]);
    }

    for (int s = 0; s < STEPS; ++s) {
        const float* u = (s == 0) ? (u_hist + (size_t)(NHIST - 1) * Q)
                                  : (out + (size_t)(s - 1) * Q);
        step_kernel<<<sgrid, NTHREADS, SM_TOTAL>>>(u, hb[s & 1], hb[(s + 1) & 1]);
        readout_kernel<<<rgrid, 256>>>(hb[(s + 1) & 1], out + (size_t)s * Q);
    }
}